// round 9
// baseline (speedup 1.0000x reference)
#include <cuda_runtime.h>
#include <cstdint>

// ---------------------------------------------------------------------------
// Problem constants
// ---------------------------------------------------------------------------
#define BB   4096
#define NN   8
#define DD   256
#define FFD  2048
#define NDIM 2048          // N*D
#define ROWS 32768         // B*N

// ---------------------------------------------------------------------------
// Scratch (device globals — no runtime allocation allowed)
// ---------------------------------------------------------------------------
__device__ float g_wt[2u * NDIM * NDIM];        // expanded circulant weights (2 halves stacked: 4096 x 2048)
__device__ float g_xn[(size_t)BB * NDIM];       // LN1 out (tf32-rounded)
__device__ float g_x [(size_t)BB * NDIM];       // post-TT residual (full fp32)
__device__ float g_yn[(size_t)BB * NDIM];       // LN2 out (tf32-rounded)
__device__ float g_hidden[(size_t)ROWS * FFD];  // FFN hidden (tf32-rounded)
__device__ float g_w1r[FFD * DD];               // W1 tf32-rounded
__device__ float g_w2r[DD * FFD];               // W2 tf32-rounded

// ---------------------------------------------------------------------------
// Helpers
// ---------------------------------------------------------------------------
__device__ __forceinline__ float to_tf32(float x) {
    float r;
    asm("cvt.rna.tf32.f32 %0, %1;" : "=f"(r) : "f"(x));
    return r;
}

__device__ __forceinline__ uint32_t smem_u32(const void* p) {
    uint32_t a;
    asm("{ .reg .u64 t; cvta.to.shared.u64 t, %1; cvt.u32.u64 %0, t; }"
        : "=r"(a) : "l"(p));
    return a;
}

#define CP_ASYNC16(dst_u32, src_ptr) \
    asm volatile("cp.async.cg.shared.global [%0], [%1], 16;" \
                 :: "r"(dst_u32), "l"(src_ptr) : "memory")
#define CP_COMMIT() asm volatile("cp.async.commit_group;" ::: "memory")
#define CP_WAIT2()  asm volatile("cp.async.wait_group 2;" ::: "memory")
#define CP_WAIT1()  asm volatile("cp.async.wait_group 1;" ::: "memory")
#define CP_WAIT0()  asm volatile("cp.async.wait_group 0;" ::: "memory")

// ldmatrix.x4 on 32-bit (tf32) data: b16 pair packing reconstitutes tf32 words.
#define LDSM_X4(r0, r1, r2, r3, addr) \
    asm volatile("ldmatrix.sync.aligned.m8n8.x4.shared.b16 {%0,%1,%2,%3}, [%4];" \
                 : "=r"(r0), "=r"(r1), "=r"(r2), "=r"(r3) : "r"(addr))

__device__ __forceinline__ void mma_tf32(float& c0, float& c1, float& c2, float& c3,
                                         uint32_t a0, uint32_t a1, uint32_t a2, uint32_t a3,
                                         uint32_t b0, uint32_t b1) {
    asm volatile(
        "mma.sync.aligned.m16n8k8.row.col.f32.tf32.tf32.f32 "
        "{%0,%1,%2,%3}, {%4,%5,%6,%7}, {%8,%9}, {%0,%1,%2,%3};"
        : "+f"(c0), "+f"(c1), "+f"(c2), "+f"(c3)
        : "r"(a0), "r"(a1), "r"(a2), "r"(a3), "r"(b0), "r"(b1));
}

// ---------------------------------------------------------------------------
// Weight expansion + rounding
// Wt[jcol = kk*D+o][p = i*D+d] = w[d,o,(kk-i)%8]
// ---------------------------------------------------------------------------
__global__ void expand_w(const float* __restrict__ w_in, const float* __restrict__ w_out)
{
    int idx = blockIdx.x * blockDim.x + threadIdx.x;
    if (idx >= NDIM * NDIM) return;
    int j = idx >> 11;
    int p = idx & 2047;
    int kk = j >> 8, o = j & 255;
    int i  = p >> 8, d = p & 255;
    int s  = (kk - i + 8) & 7;
    int widx = (d * DD + o) * NN + s;
    g_wt[idx]               = to_tf32(w_in [widx]);
    g_wt[NDIM * NDIM + idx] = to_tf32(w_out[widx]);
}

__global__ void round_w(const float* __restrict__ W1, const float* __restrict__ W2)
{
    int idx = blockIdx.x * blockDim.x + threadIdx.x;
    g_w1r[idx] = to_tf32(W1[idx]);
    g_w2r[idx] = to_tf32(W2[idx]);
}

// ---------------------------------------------------------------------------
// LayerNorm over D=256, one warp per row; output tf32-rounded
// ---------------------------------------------------------------------------
template<int PH>
__global__ __launch_bounds__(256) void ln_kernel(const float* __restrict__ xin_ext,
                                                 const float* __restrict__ gamma,
                                                 const float* __restrict__ beta)
{
    const float* x   = (PH == 0) ? xin_ext : g_x;
    float*       out = (PH == 0) ? g_xn    : g_yn;

    int warp = threadIdx.x >> 5;
    int lane = threadIdx.x & 31;
    int row  = blockIdx.x * 8 + warp;

    const float* xr = x + (size_t)row * DD;
    float v[8];
    float sum = 0.f;
#pragma unroll
    for (int i = 0; i < 8; i++) { v[i] = xr[lane + 32 * i]; sum += v[i]; }
#pragma unroll
    for (int off = 16; off; off >>= 1) sum += __shfl_xor_sync(0xffffffffu, sum, off);
    float mu = sum * (1.f / 256.f);

    float var = 0.f;
#pragma unroll
    for (int i = 0; i < 8; i++) { float t = v[i] - mu; var += t * t; }
#pragma unroll
    for (int off = 16; off; off >>= 1) var += __shfl_xor_sync(0xffffffffu, var, off);
    float rstd = rsqrtf(var * (1.f / 256.f) + 1e-5f);

    float* orow = out + (size_t)row * DD;
#pragma unroll
    for (int i = 0; i < 8; i++) {
        int c = lane + 32 * i;
        orow[c] = to_tf32((v[i] - mu) * rstd * gamma[c] + beta[c]);
    }
}

// ---------------------------------------------------------------------------
// tf32 mma.sync GEMM, ldmatrix fragment loads, SOFTWARE-PIPELINED fragments:
// fragments for step ka+1 load while step ka computes (register dbl-buffer);
// cross-tile preload after end-of-tile wait+barrier. 3-stage cp.async,
// 2 CTAs/SM. BM=128 BN=128 BK=32, 2x4 warps, warp tile 64x32.
//
// MODE 0: TT (A=g_xn K=2048, Bt=g_wt rows [bn + halfsel*2048], +res(ent) -> g_x)
// MODE 1: FFN1 (A=g_yn K=256, Bt=g_w1r, relu(+bias1), tf32-round -> g_hidden)
// MODE 2: FFN2 (A=g_hidden K=2048, Bt=g_w2r, +bias2 +g_x -> out)
// ---------------------------------------------------------------------------
#define BM 128
#define BN 128
#define BK 32
#define PITCH 36                       // floats per smem row (32 + 4 pad)
#define TILE_FLOATS (128 * PITCH)
#define TILE_BYTES  (TILE_FLOATS * 4)
#define STAGE_FLOATS (2 * TILE_FLOATS)
#define STAGE_BYTES (STAGE_FLOATS * 4)
#define NSTAGE 3
#define GEMM_SMEM (NSTAGE * STAGE_BYTES)

template<int MODE>
__global__ __launch_bounds__(256, 2) void gemm_mma(
    const float* __restrict__ bias,
    const float* __restrict__ res,
    float* __restrict__ C)
{
    constexpr int K    = (MODE == 1) ? 256 : 2048;
    constexpr int Ncol = (MODE == 2) ? 256 : 2048;
    constexpr int KT   = K / BK;        // >= 8 in all modes

    const float* A;
    const float* Bt;
    if constexpr (MODE == 0)      { A = g_xn;     Bt = g_wt;  }
    else if constexpr (MODE == 1) { A = g_yn;     Bt = g_w1r; }
    else                          { A = g_hidden; Bt = g_w2r; }

    extern __shared__ float sm[];

    int tid  = threadIdx.x;
    int wid  = tid >> 5;
    int lane = tid & 31;
    int g    = lane >> 2;
    int tg   = lane & 3;
    int wm   = wid & 1;
    int wn   = wid >> 1;

    int bm = blockIdx.y * BM;
    int bn = blockIdx.x * BN;
    int brow = bn;
    if (MODE == 0 && bm >= 2048) brow += 2048;

    // cp.async: thread t covers row = t>>1, 4 x 16B segs
    int ldrow = tid >> 1;
    int ldseg = (tid & 1) * 4;

    const char* Abase = (const char*)(A  + (size_t)(bm   + ldrow) * K) + ldseg * 16;
    const char* Bbase = (const char*)(Bt + (size_t)(brow + ldrow) * K) + ldseg * 16;
    uint32_t smbase = smem_u32(sm);
    uint32_t sA = smbase + (uint32_t)(ldrow * PITCH * 4 + ldseg * 16);
    uint32_t sB = sA + TILE_BYTES;

    auto prefetch = [&](int kt) {
        uint32_t off = (uint32_t)((kt % NSTAGE) * STAGE_BYTES);
        const char* ag = Abase + (size_t)kt * BK * 4;
        const char* bg = Bbase + (size_t)kt * BK * 4;
#pragma unroll
        for (int s = 0; s < 4; s++) {
            CP_ASYNC16(sA + off + s * 16, ag + s * 16);
            CP_ASYNC16(sB + off + s * 16, bg + s * 16);
        }
    };

    // ldmatrix per-lane addresses
    int r   = lane & 7;
    int sel = lane >> 3;
    uint32_t aAddr[4], bAddr[2];
#pragma unroll
    for (int mi = 0; mi < 4; mi++)
        aAddr[mi] = smbase +
            4u * ((uint32_t)(wm * 64 + mi * 16 + r + (sel & 1) * 8) * PITCH + (sel >> 1) * 4);
#pragma unroll
    for (int ni2 = 0; ni2 < 2; ni2++)
        bAddr[ni2] = smbase + TILE_BYTES +
            4u * ((uint32_t)(wn * 32 + ni2 * 16 + r + (sel >> 1) * 8) * PITCH + (sel & 1) * 4);

    // Double-buffered fragments
    uint32_t af[2][4][4];
    uint32_t bf[2][4][2];

    float acc[4][4][4];
#pragma unroll
    for (int mi = 0; mi < 4; mi++)
#pragma unroll
        for (int ni = 0; ni < 4; ni++)
#pragma unroll
            for (int c = 0; c < 4; c++) acc[mi][ni][c] = 0.f;

    // frag preload of one ka-step (byte offset within smem) into buffer b
    auto preload = [&](uint32_t koff, int b) {
        LDSM_X4(bf[b][0][0], bf[b][0][1], bf[b][1][0], bf[b][1][1], bAddr[0] + koff);
        LDSM_X4(bf[b][2][0], bf[b][2][1], bf[b][3][0], bf[b][3][1], bAddr[1] + koff);
#pragma unroll
        for (int mi = 0; mi < 4; mi++)
            LDSM_X4(af[b][mi][0], af[b][mi][1], af[b][mi][2], af[b][mi][3],
                    aAddr[mi] + koff);
    };

    auto compute = [&](int b) {
#pragma unroll
        for (int mi = 0; mi < 4; mi++)
#pragma unroll
            for (int ni = 0; ni < 4; ni++)
                mma_tf32(acc[mi][ni][0], acc[mi][ni][1], acc[mi][ni][2], acc[mi][ni][3],
                         af[b][mi][0], af[b][mi][1], af[b][mi][2], af[b][mi][3],
                         bf[b][ni][0], bf[b][ni][1]);
    };

    // ---- prologue: 3 tile loads in flight; tile 0 resident; frags (0,0) in buf0
    prefetch(0); CP_COMMIT();
    prefetch(1); CP_COMMIT();
    prefetch(2); CP_COMMIT();
    CP_WAIT2();            // tile 0 complete (this thread)
    __syncthreads();       // ...and visible to all
    preload(0u * STAGE_BYTES + 0u, 0);

    // ---- mainloop. Buffer parity invariant: tile starts with frags in buf0.
    for (int kt = 0; kt < KT; kt++) {
        uint32_t stoff = (uint32_t)((kt % NSTAGE) * STAGE_BYTES);

        // ka = 0..2: preload ka+1 into alternating buffer, compute current
        preload(stoff + 1 * 32, 1);  compute(0);
        preload(stoff + 2 * 32, 0);  compute(1);
        preload(stoff + 3 * 32, 1);  compute(0);
        // ka = 3: compute only
        compute(1);

        if (kt + 1 < KT) {
            // tile kt+1 resident after this wait (one group — tile kt+2 — stays in flight)
            if (kt + 2 < KT) CP_WAIT1(); else CP_WAIT0();
            __syncthreads();   // cross-thread visibility of tile kt+1 + reuse guard
            uint32_t nstoff = (uint32_t)(((kt + 1) % NSTAGE) * STAGE_BYTES);
            preload(nstoff + 0u, 0);          // next tile ka=0 -> buf0 (invariant)
            if (kt + 3 < KT) { prefetch(kt + 3); CP_COMMIT(); }
        }
    }

    // ---- epilogue ----
#pragma unroll
    for (int mi = 0; mi < 4; mi++) {
#pragma unroll
        for (int half = 0; half < 2; half++) {
            int row = bm + wm * 64 + mi * 16 + g + half * 8;
#pragma unroll
            for (int ni = 0; ni < 4; ni++) {
                int col = bn + wn * 32 + ni * 8 + tg * 2;
                float v0 = acc[mi][ni][half * 2 + 0];
                float v1 = acc[mi][ni][half * 2 + 1];
                if constexpr (MODE == 0) {
                    const float2 rv = *(const float2*)&res[(size_t)row * 2048 + col];
                    v0 += rv.x; v1 += rv.y;
                } else if constexpr (MODE == 1) {
                    v0 = to_tf32(fmaxf(v0 + bias[col],     0.f));
                    v1 = to_tf32(fmaxf(v1 + bias[col + 1], 0.f));
                } else {
                    const float2 rv = *(const float2*)&res[(size_t)row * 256 + col];
                    v0 += bias[col]     + rv.x;
                    v1 += bias[col + 1] + rv.y;
                }
                float2 o; o.x = v0; o.y = v1;
                *(float2*)&C[(size_t)row * Ncol + col] = o;
            }
        }
    }
}

// ---------------------------------------------------------------------------
// Host side
// ---------------------------------------------------------------------------
extern "C" void kernel_launch(void* const* d_in, const int* in_sizes, int n_in,
                              void* d_out, int out_size)
{
    const float* ent    = (const float*)d_in[0];
    const float* w_in   = (const float*)d_in[1];
    const float* w_out  = (const float*)d_in[2];
    const float* W1     = (const float*)d_in[3];
    const float* bias1  = (const float*)d_in[4];
    const float* W2     = (const float*)d_in[5];
    const float* bias2  = (const float*)d_in[6];
    const float* gamma1 = (const float*)d_in[7];
    const float* beta1  = (const float*)d_in[8];
    const float* gamma2 = (const float*)d_in[9];
    const float* beta2  = (const float*)d_in[10];
    float* out = (float*)d_out;

    void* p_x;
    void* p_hid;
    cudaGetSymbolAddress(&p_x,   g_x);
    cudaGetSymbolAddress(&p_hid, g_hidden);

    static bool attr_done = false;
    if (!attr_done) {
        cudaFuncSetAttribute(gemm_mma<0>, cudaFuncAttributeMaxDynamicSharedMemorySize, GEMM_SMEM);
        cudaFuncSetAttribute(gemm_mma<1>, cudaFuncAttributeMaxDynamicSharedMemorySize, GEMM_SMEM);
        cudaFuncSetAttribute(gemm_mma<2>, cudaFuncAttributeMaxDynamicSharedMemorySize, GEMM_SMEM);
        attr_done = true;
    }

    // 1. expand circulant weights + round W1/W2 to tf32
    expand_w<<<(NDIM * NDIM + 255) / 256, 256>>>(w_in, w_out);
    round_w<<<(FFD * DD) / 256, 256>>>(W1, W2);

    // 2. LN1: ent -> g_xn (tf32)
    ln_kernel<0><<<ROWS / 8, 256>>>(ent, gamma1, beta1);

    // 3. TT GEMM + residual: g_x = ent + g_xn @ Wbig^T  (4096 x 2048)
    gemm_mma<0><<<dim3(2048 / BN, 4096 / BM), 256, GEMM_SMEM>>>(nullptr, ent, (float*)p_x);

    // 4. LN2: g_x -> g_yn (tf32)
    ln_kernel<1><<<ROWS / 8, 256>>>(nullptr, gamma2, beta2);

    // 5. FFN1: g_hidden = tf32(relu(g_yn @ W1^T + b1))  (32768 x 2048)
    gemm_mma<1><<<dim3(2048 / BN, 32768 / BM), 256, GEMM_SMEM>>>(bias1, nullptr, (float*)p_hid);

    // 6. FFN2: out = g_x + g_hidden @ W2^T + b2  (32768 x 256)
    gemm_mma<2><<<dim3(256 / BN, 32768 / BM), 256, GEMM_SMEM>>>(bias2, (const float*)p_x, out);
}

// round 13
// speedup vs baseline: 1.1792x; 1.1792x over previous
#include <cuda_runtime.h>
#include <cuda_fp16.h>
#include <cstdint>

// ---------------------------------------------------------------------------
// Problem constants
// ---------------------------------------------------------------------------
#define BB   4096
#define NN   8
#define DD   256
#define FFD  2048
#define NDIM 2048          // N*D
#define ROWS 32768         // B*N

// ---------------------------------------------------------------------------
// Scratch (device globals — no runtime allocation allowed)
// ---------------------------------------------------------------------------
__device__ __half g_wt[2u * NDIM * NDIM];         // expanded circulant weights (fp16, 2 halves stacked)
__device__ __half g_xn[(size_t)BB * NDIM];        // LN1 out (fp16)
__device__ float  g_x [(size_t)BB * NDIM];        // post-TT residual (fp32)
__device__ __half g_yn[(size_t)BB * NDIM];        // LN2 out (fp16)
__device__ __half g_hidden[(size_t)ROWS * FFD];   // FFN hidden (fp16)
__device__ __half g_w1h[FFD * DD];                // W1 fp16
__device__ __half g_w2h[DD * FFD];                // W2 fp16

// ---------------------------------------------------------------------------
// Helpers
// ---------------------------------------------------------------------------
__device__ __forceinline__ uint32_t smem_u32(const void* p) {
    uint32_t a;
    asm("{ .reg .u64 t; cvta.to.shared.u64 t, %1; cvt.u32.u64 %0, t; }"
        : "=r"(a) : "l"(p));
    return a;
}

#define CP_ASYNC16(dst_u32, src_ptr) \
    asm volatile("cp.async.cg.shared.global [%0], [%1], 16;" \
                 :: "r"(dst_u32), "l"(src_ptr) : "memory")
#define CP_COMMIT() asm volatile("cp.async.commit_group;" ::: "memory")
#define CP_WAIT2()  asm volatile("cp.async.wait_group 2;" ::: "memory")
#define CP_WAIT1()  asm volatile("cp.async.wait_group 1;" ::: "memory")
#define CP_WAIT0()  asm volatile("cp.async.wait_group 0;" ::: "memory")

#define LDSM_X4(r0, r1, r2, r3, addr) \
    asm volatile("ldmatrix.sync.aligned.m8n8.x4.shared.b16 {%0,%1,%2,%3}, [%4];" \
                 : "=r"(r0), "=r"(r1), "=r"(r2), "=r"(r3) : "r"(addr))

// fp16 MMA, fp32 accumulate: m16n8k16
__device__ __forceinline__ void mma_f16(float& c0, float& c1, float& c2, float& c3,
                                        uint32_t a0, uint32_t a1, uint32_t a2, uint32_t a3,
                                        uint32_t b0, uint32_t b1) {
    asm volatile(
        "mma.sync.aligned.m16n8k16.row.col.f32.f16.f16.f32 "
        "{%0,%1,%2,%3}, {%4,%5,%6,%7}, {%8,%9}, {%0,%1,%2,%3};"
        : "+f"(c0), "+f"(c1), "+f"(c2), "+f"(c3)
        : "r"(a0), "r"(a1), "r"(a2), "r"(a3), "r"(b0), "r"(b1));
}

// ---------------------------------------------------------------------------
// Weight expansion + rounding (fp16 outputs)
// Wt[jcol = kk*D+o][p = i*D+d] = w[d,o,(kk-i)%8]
// ---------------------------------------------------------------------------
__global__ void expand_w(const float* __restrict__ w_in, const float* __restrict__ w_out)
{
    int idx = blockIdx.x * blockDim.x + threadIdx.x;
    if (idx >= NDIM * NDIM) return;
    int j = idx >> 11;
    int p = idx & 2047;
    int kk = j >> 8, o = j & 255;
    int i  = p >> 8, d = p & 255;
    int s  = (kk - i + 8) & 7;
    int widx = (d * DD + o) * NN + s;
    g_wt[idx]               = __float2half_rn(w_in [widx]);
    g_wt[NDIM * NDIM + idx] = __float2half_rn(w_out[widx]);
}

__global__ void round_w(const float* __restrict__ W1, const float* __restrict__ W2)
{
    int idx = blockIdx.x * blockDim.x + threadIdx.x;
    g_w1h[idx] = __float2half_rn(W1[idx]);
    g_w2h[idx] = __float2half_rn(W2[idx]);
}

// ---------------------------------------------------------------------------
// LayerNorm over D=256, one warp per row; fp16 output
// ---------------------------------------------------------------------------
template<int PH>
__global__ __launch_bounds__(256) void ln_kernel(const float* __restrict__ xin_ext,
                                                 const float* __restrict__ gamma,
                                                 const float* __restrict__ beta)
{
    const float* x    = (PH == 0) ? xin_ext : g_x;
    __half*      out  = (PH == 0) ? g_xn    : g_yn;

    int warp = threadIdx.x >> 5;
    int lane = threadIdx.x & 31;
    int row  = blockIdx.x * 8 + warp;

    const float* xr = x + (size_t)row * DD;
    float v[8];
    float sum = 0.f;
#pragma unroll
    for (int i = 0; i < 8; i++) { v[i] = xr[lane + 32 * i]; sum += v[i]; }
#pragma unroll
    for (int off = 16; off; off >>= 1) sum += __shfl_xor_sync(0xffffffffu, sum, off);
    float mu = sum * (1.f / 256.f);

    float var = 0.f;
#pragma unroll
    for (int i = 0; i < 8; i++) { float t = v[i] - mu; var += t * t; }
#pragma unroll
    for (int off = 16; off; off >>= 1) var += __shfl_xor_sync(0xffffffffu, var, off);
    float rstd = rsqrtf(var * (1.f / 256.f) + 1e-5f);

    __half* orow = out + (size_t)row * DD;
#pragma unroll
    for (int i = 0; i < 8; i++) {
        int c = lane + 32 * i;
        orow[c] = __float2half_rn((v[i] - mu) * rstd * gamma[c] + beta[c]);
    }
}

// ---------------------------------------------------------------------------
// fp16 mma.sync (m16n8k16) GEMM, ldmatrix fragment loads, software-pipelined
// fragments, 3-stage cp.async, 2 CTAs/SM.
// BM=128 BN=128 BK=64 (halfs), 2x4 warps, warp tile 64x32, 4 k16-steps/tile.
//
// MODE 0: TT (A=g_xn K=2048, Bt=g_wt rows [bn + halfsel*2048], +res(ent) -> g_x fp32)
// MODE 1: FFN1 (A=g_yn K=256, Bt=g_w1h, relu(+bias1) -> g_hidden fp16)
// MODE 2: FFN2 (A=g_hidden K=2048, Bt=g_w2h, +bias2 +g_x -> out fp32)
// ---------------------------------------------------------------------------
#define BM 128
#define BN 128
#define BK 64
#define PITCH_B 144                      // bytes per smem row (128 data + 16 pad)
#define TILE_BYTES (128 * PITCH_B)       // 18432 B, one matrix one stage
#define STAGE_BYTES (2 * TILE_BYTES)     // A + B = 36864 B
#define NSTAGE 3
#define GEMM_SMEM (NSTAGE * STAGE_BYTES) // 110592 B

template<int MODE>
__global__ __launch_bounds__(256, 2) void gemm_mma(
    const float* __restrict__ bias,
    const float* __restrict__ res,
    void* __restrict__ Cout)
{
    constexpr int K    = (MODE == 1) ? 256 : 2048;
    constexpr int Ncol = (MODE == 2) ? 256 : 2048;
    constexpr int KT   = K / BK;        // 32 / 4 / 32

    const __half* A;
    const __half* Bt;
    if constexpr (MODE == 0)      { A = g_xn;     Bt = g_wt;  }
    else if constexpr (MODE == 1) { A = g_yn;     Bt = g_w1h; }
    else                          { A = g_hidden; Bt = g_w2h; }

    extern __shared__ char sm[];

    int tid  = threadIdx.x;
    int wid  = tid >> 5;
    int lane = tid & 31;
    int g    = lane >> 2;
    int tg   = lane & 3;
    int wm   = wid & 1;
    int wn   = wid >> 1;

    int bm = blockIdx.y * BM;
    int bn = blockIdx.x * BN;
    int brow = bn;
    if (MODE == 0 && bm >= 2048) brow += 2048;

    // cp.async: thread t covers row = t>>1, 4 x 16B segs at (t&1)*64B
    int ldrow = tid >> 1;
    int ldseg = (tid & 1) * 64;

    const char* Abase = (const char*)(A  + (size_t)(bm   + ldrow) * K) + ldseg;
    const char* Bbase = (const char*)(Bt + (size_t)(brow + ldrow) * K) + ldseg;
    uint32_t smbase = smem_u32(sm);
    uint32_t sA = smbase + (uint32_t)(ldrow * PITCH_B + ldseg);
    uint32_t sB = sA + TILE_BYTES;

    auto prefetch = [&](int kt) {
        uint32_t off = (uint32_t)((kt % NSTAGE) * STAGE_BYTES);
        const char* ag = Abase + (size_t)kt * BK * 2;   // BK halfs = 128 B
        const char* bg = Bbase + (size_t)kt * BK * 2;
#pragma unroll
        for (int s = 0; s < 4; s++) {
            CP_ASYNC16(sA + off + s * 16, ag + s * 16);
            CP_ASYNC16(sB + off + s * 16, bg + s * 16);
        }
    };

    // ldmatrix per-lane addresses.
    // A (per mi): r0=(rows m0+g, k0-7) r1=(+8 rows) r2=(k8-15) r3=(+8, k8-15)
    //   lane sel: row += (sel&1)*8, kbyte += (sel>>1)*16
    // B (per ni2 = ni pair): r0=(n-block, k0-7) r1=(n-block, k8-15) r2,r3=(+8 n)
    //   lane sel: row += (sel>>1)*8, kbyte += (sel&1)*16
    int r   = lane & 7;
    int sel = lane >> 3;
    uint32_t aAddr[4], bAddr[2];
#pragma unroll
    for (int mi = 0; mi < 4; mi++)
        aAddr[mi] = smbase +
            (uint32_t)(wm * 64 + mi * 16 + r + (sel & 1) * 8) * PITCH_B + (sel >> 1) * 16;
#pragma unroll
    for (int ni2 = 0; ni2 < 2; ni2++)
        bAddr[ni2] = smbase + TILE_BYTES +
            (uint32_t)(wn * 32 + ni2 * 16 + r + (sel >> 1) * 8) * PITCH_B + (sel & 1) * 16;

    // Double-buffered fragments
    uint32_t af[2][4][4];
    uint32_t bf[2][4][2];

    float acc[4][4][4];
#pragma unroll
    for (int mi = 0; mi < 4; mi++)
#pragma unroll
        for (int ni = 0; ni < 4; ni++)
#pragma unroll
            for (int c = 0; c < 4; c++) acc[mi][ni][c] = 0.f;

    // preload one k16-step (byte offset koff within stage) into buffer b
    auto preload = [&](uint32_t koff, int b) {
        LDSM_X4(bf[b][0][0], bf[b][0][1], bf[b][1][0], bf[b][1][1], bAddr[0] + koff);
        LDSM_X4(bf[b][2][0], bf[b][2][1], bf[b][3][0], bf[b][3][1], bAddr[1] + koff);
#pragma unroll
        for (int mi = 0; mi < 4; mi++)
            LDSM_X4(af[b][mi][0], af[b][mi][1], af[b][mi][2], af[b][mi][3],
                    aAddr[mi] + koff);
    };

    auto compute = [&](int b) {
#pragma unroll
        for (int mi = 0; mi < 4; mi++)
#pragma unroll
            for (int ni = 0; ni < 4; ni++)
                mma_f16(acc[mi][ni][0], acc[mi][ni][1], acc[mi][ni][2], acc[mi][ni][3],
                        af[b][mi][0], af[b][mi][1], af[b][mi][2], af[b][mi][3],
                        bf[b][ni][0], bf[b][ni][1]);
    };

    // ---- prologue: 3 tile loads in flight; tile 0 resident; frags (0, ka=0) in buf0
    prefetch(0); CP_COMMIT();
    prefetch(1); CP_COMMIT();
    prefetch(2); CP_COMMIT();
    CP_WAIT2();
    __syncthreads();
    preload(0u, 0);

    // ---- mainloop (4 k16-steps per tile; buffer parity invariant: start buf0)
    for (int kt = 0; kt < KT; kt++) {
        uint32_t stoff = (uint32_t)((kt % NSTAGE) * STAGE_BYTES);

        preload(stoff + 1 * 32, 1);  compute(0);   // k16 step 1 while computing 0
        preload(stoff + 2 * 32, 0);  compute(1);
        preload(stoff + 3 * 32, 1);  compute(0);
        compute(1);

        if (kt + 1 < KT) {
            if (kt + 2 < KT) CP_WAIT1(); else CP_WAIT0();
            __syncthreads();
            uint32_t nstoff = (uint32_t)(((kt + 1) % NSTAGE) * STAGE_BYTES);
            preload(nstoff + 0u, 0);
            if (kt + 3 < KT) { prefetch(kt + 3); CP_COMMIT(); }
        }
    }

    // ---- epilogue ----
#pragma unroll
    for (int mi = 0; mi < 4; mi++) {
#pragma unroll
        for (int half = 0; half < 2; half++) {
            int row = bm + wm * 64 + mi * 16 + g + half * 8;
#pragma unroll
            for (int ni = 0; ni < 4; ni++) {
                int col = bn + wn * 32 + ni * 8 + tg * 2;
                float v0 = acc[mi][ni][half * 2 + 0];
                float v1 = acc[mi][ni][half * 2 + 1];
                if constexpr (MODE == 0) {
                    const float2 rv = *(const float2*)&res[(size_t)row * 2048 + col];
                    v0 += rv.x; v1 += rv.y;
                    float2 o; o.x = v0; o.y = v1;
                    *(float2*)&((float*)Cout)[(size_t)row * Ncol + col] = o;
                } else if constexpr (MODE == 1) {
                    v0 = fmaxf(v0 + bias[col],     0.f);
                    v1 = fmaxf(v1 + bias[col + 1], 0.f);
                    __half2 h = __floats2half2_rn(v0, v1);
                    *(__half2*)&((__half*)Cout)[(size_t)row * Ncol + col] = h;
                } else {
                    const float2 rv = *(const float2*)&res[(size_t)row * 256 + col];
                    v0 += bias[col]     + rv.x;
                    v1 += bias[col + 1] + rv.y;
                    float2 o; o.x = v0; o.y = v1;
                    *(float2*)&((float*)Cout)[(size_t)row * Ncol + col] = o;
                }
            }
        }
    }
}

// ---------------------------------------------------------------------------
// Host side
// ---------------------------------------------------------------------------
extern "C" void kernel_launch(void* const* d_in, const int* in_sizes, int n_in,
                              void* d_out, int out_size)
{
    const float* ent    = (const float*)d_in[0];
    const float* w_in   = (const float*)d_in[1];
    const float* w_out  = (const float*)d_in[2];
    const float* W1     = (const float*)d_in[3];
    const float* bias1  = (const float*)d_in[4];
    const float* W2     = (const float*)d_in[5];
    const float* bias2  = (const float*)d_in[6];
    const float* gamma1 = (const float*)d_in[7];
    const float* beta1  = (const float*)d_in[8];
    const float* gamma2 = (const float*)d_in[9];
    const float* beta2  = (const float*)d_in[10];
    float* out = (float*)d_out;

    void* p_x;
    void* p_hid;
    cudaGetSymbolAddress(&p_x,   g_x);
    cudaGetSymbolAddress(&p_hid, g_hidden);

    static bool attr_done = false;
    if (!attr_done) {
        cudaFuncSetAttribute(gemm_mma<0>, cudaFuncAttributeMaxDynamicSharedMemorySize, GEMM_SMEM);
        cudaFuncSetAttribute(gemm_mma<1>, cudaFuncAttributeMaxDynamicSharedMemorySize, GEMM_SMEM);
        cudaFuncSetAttribute(gemm_mma<2>, cudaFuncAttributeMaxDynamicSharedMemorySize, GEMM_SMEM);
        attr_done = true;
    }

    // 1. expand circulant weights + round W1/W2 to fp16
    expand_w<<<(NDIM * NDIM + 255) / 256, 256>>>(w_in, w_out);
    round_w<<<(FFD * DD) / 256, 256>>>(W1, W2);

    // 2. LN1: ent -> g_xn (fp16)
    ln_kernel<0><<<ROWS / 8, 256>>>(ent, gamma1, beta1);

    // 3. TT GEMM + residual: g_x = ent + g_xn @ Wbig^T  (4096 x 2048)
    gemm_mma<0><<<dim3(2048 / BN, 4096 / BM), 256, GEMM_SMEM>>>(nullptr, ent, p_x);

    // 4. LN2: g_x -> g_yn (fp16)
    ln_kernel<1><<<ROWS / 8, 256>>>(nullptr, gamma2, beta2);

    // 5. FFN1: g_hidden = fp16(relu(g_yn @ W1^T + b1))  (32768 x 2048)
    gemm_mma<1><<<dim3(2048 / BN, 32768 / BM), 256, GEMM_SMEM>>>(bias1, nullptr, p_hid);

    // 6. FFN2: out = g_x + g_hidden @ W2^T + b2  (32768 x 256)
    gemm_mma<2><<<dim3(256 / BN, 32768 / BM), 256, GEMM_SMEM>>>(bias2, (const float*)p_x, out);
}

// round 15
// speedup vs baseline: 1.8069x; 1.5324x over previous
#include <cuda_runtime.h>
#include <cuda_fp16.h>
#include <cstdint>

// ---------------------------------------------------------------------------
// Problem constants
// ---------------------------------------------------------------------------
#define BB   4096
#define NN   8
#define DD   256
#define FFD  2048
#define NDIM 2048          // N*D
#define ROWS 32768         // B*N

// ---------------------------------------------------------------------------
// Scratch (device globals — no runtime allocation allowed)
// ---------------------------------------------------------------------------
__device__ __half g_wt[2u * NDIM * NDIM];         // expanded circulant weights (fp16, 2 halves stacked)
__device__ __half g_xn[(size_t)BB * NDIM];        // LN1 out (fp16)
__device__ float  g_x [(size_t)BB * NDIM];        // post-TT residual (fp32)
__device__ __half g_yn[(size_t)BB * NDIM];        // LN2 out (fp16)
__device__ __half g_hidden[(size_t)ROWS * FFD];   // FFN hidden (fp16)
__device__ __half g_w1h[FFD * DD];                // W1 fp16
__device__ __half g_w2h[DD * FFD];                // W2 fp16

// ---------------------------------------------------------------------------
// Helpers
// ---------------------------------------------------------------------------
__device__ __forceinline__ uint32_t smem_u32(const void* p) {
    uint32_t a;
    asm("{ .reg .u64 t; cvta.to.shared.u64 t, %1; cvt.u32.u64 %0, t; }"
        : "=r"(a) : "l"(p));
    return a;
}

#define CP_ASYNC16(dst_u32, src_ptr) \
    asm volatile("cp.async.cg.shared.global [%0], [%1], 16;" \
                 :: "r"(dst_u32), "l"(src_ptr) : "memory")
#define CP_COMMIT() asm volatile("cp.async.commit_group;" ::: "memory")
#define CP_WAIT0()  asm volatile("cp.async.wait_group 0;" ::: "memory")

#define LDSM_X4(r0, r1, r2, r3, addr) \
    asm volatile("ldmatrix.sync.aligned.m8n8.x4.shared.b16 {%0,%1,%2,%3}, [%4];" \
                 : "=r"(r0), "=r"(r1), "=r"(r2), "=r"(r3) : "r"(addr))

// fp16 MMA, fp32 accumulate: m16n8k16
__device__ __forceinline__ void mma_f16(float& c0, float& c1, float& c2, float& c3,
                                        uint32_t a0, uint32_t a1, uint32_t a2, uint32_t a3,
                                        uint32_t b0, uint32_t b1) {
    asm volatile(
        "mma.sync.aligned.m16n8k16.row.col.f32.f16.f16.f32 "
        "{%0,%1,%2,%3}, {%4,%5,%6,%7}, {%8,%9}, {%0,%1,%2,%3};"
        : "+f"(c0), "+f"(c1), "+f"(c2), "+f"(c3)
        : "r"(a0), "r"(a1), "r"(a2), "r"(a3), "r"(b0), "r"(b1));
}

// ---------------------------------------------------------------------------
// Weight expansion + rounding (fp16 outputs)
// Wt[jcol = kk*D+o][p = i*D+d] = w[d,o,(kk-i)%8]
// ---------------------------------------------------------------------------
__global__ void expand_w(const float* __restrict__ w_in, const float* __restrict__ w_out)
{
    int idx = blockIdx.x * blockDim.x + threadIdx.x;
    if (idx >= NDIM * NDIM) return;
    int j = idx >> 11;
    int p = idx & 2047;
    int kk = j >> 8, o = j & 255;
    int i  = p >> 8, d = p & 255;
    int s  = (kk - i + 8) & 7;
    int widx = (d * DD + o) * NN + s;
    g_wt[idx]               = __float2half_rn(w_in [widx]);
    g_wt[NDIM * NDIM + idx] = __float2half_rn(w_out[widx]);
}

__global__ void round_w(const float* __restrict__ W1, const float* __restrict__ W2)
{
    int idx = blockIdx.x * blockDim.x + threadIdx.x;
    g_w1h[idx] = __float2half_rn(W1[idx]);
    g_w2h[idx] = __float2half_rn(W2[idx]);
}

// ---------------------------------------------------------------------------
// LayerNorm over D=256, one warp per row; fp16 output
// ---------------------------------------------------------------------------
template<int PH>
__global__ __launch_bounds__(256) void ln_kernel(const float* __restrict__ xin_ext,
                                                 const float* __restrict__ gamma,
                                                 const float* __restrict__ beta)
{
    const float* x    = (PH == 0) ? xin_ext : g_x;
    __half*      out  = (PH == 0) ? g_xn    : g_yn;

    int warp = threadIdx.x >> 5;
    int lane = threadIdx.x & 31;
    int row  = blockIdx.x * 8 + warp;

    const float* xr = x + (size_t)row * DD;
    float v[8];
    float sum = 0.f;
#pragma unroll
    for (int i = 0; i < 8; i++) { v[i] = xr[lane + 32 * i]; sum += v[i]; }
#pragma unroll
    for (int off = 16; off; off >>= 1) sum += __shfl_xor_sync(0xffffffffu, sum, off);
    float mu = sum * (1.f / 256.f);

    float var = 0.f;
#pragma unroll
    for (int i = 0; i < 8; i++) { float t = v[i] - mu; var += t * t; }
#pragma unroll
    for (int off = 16; off; off >>= 1) var += __shfl_xor_sync(0xffffffffu, var, off);
    float rstd = rsqrtf(var * (1.f / 256.f) + 1e-5f);

    __half* orow = out + (size_t)row * DD;
#pragma unroll
    for (int i = 0; i < 8; i++) {
        int c = lane + 32 * i;
        orow[c] = __float2half_rn((v[i] - mu) * rstd * gamma[c] + beta[c]);
    }
}

// ---------------------------------------------------------------------------
// fp16 mma.sync (m16n8k16) GEMM, 3 CTAs/SM (24 warps).
// BM=64 BN=128 BK=64 halfs, 256 threads = 2(M) x 4(N) warps, warp tile 32x32,
// 2-stage cp.async, ldmatrix fragment loads, ~80-reg budget (no spills).
//
// MODE 0: TT (A=g_xn K=2048, Bt=g_wt rows [bn + halfsel*2048], +res(ent) -> g_x fp32)
// MODE 1: FFN1 (A=g_yn K=256, Bt=g_w1h, relu(+bias1) -> g_hidden fp16)
// MODE 2: FFN2 (A=g_hidden K=2048, Bt=g_w2h, +bias2 +g_x -> out fp32)
// ---------------------------------------------------------------------------
#define BM 64
#define BN 128
#define BK 64
#define PITCH_B 144                        // bytes per smem row (128 data + 16 pad)
#define A_TILE_BYTES (64 * PITCH_B)        // 9216
#define B_TILE_BYTES (128 * PITCH_B)       // 18432
#define STAGE_BYTES (A_TILE_BYTES + B_TILE_BYTES)  // 27648
#define NSTAGE 2
#define GEMM_SMEM (NSTAGE * STAGE_BYTES)   // 55296

template<int MODE>
__global__ __launch_bounds__(256, 3) void gemm_mma(
    const float* __restrict__ bias,
    const float* __restrict__ res,
    void* __restrict__ Cout)
{
    constexpr int K    = (MODE == 1) ? 256 : 2048;
    constexpr int Ncol = (MODE == 2) ? 256 : 2048;
    constexpr int KT   = K / BK;          // 32 / 4 / 32

    const __half* A;
    const __half* Bt;
    if constexpr (MODE == 0)      { A = g_xn;     Bt = g_wt;  }
    else if constexpr (MODE == 1) { A = g_yn;     Bt = g_w1h; }
    else                          { A = g_hidden; Bt = g_w2h; }

    extern __shared__ char sm[];

    int tid  = threadIdx.x;
    int wid  = tid >> 5;
    int lane = tid & 31;
    int g    = lane >> 2;
    int tg   = lane & 3;
    int wm   = wid & 1;       // M warp (0..1), 32 rows each
    int wn   = wid >> 1;      // N warp (0..3), 32 cols each

    int bm = blockIdx.y * BM;
    int bn = blockIdx.x * BN;
    int brow = bn;
    if (MODE == 0 && bm >= 2048) brow += 2048;   // second-half weight block

    // cp.async mapping:
    // A: 64 rows x 128B; thread t: row = t>>2, two 16B chunks at (t&3)*16 and +64
    // B: 128 rows x 128B; thread t: row = t>>1, four 16B chunks in (t&1)*64..+63
    int arow = tid >> 2, acol = (tid & 3) * 16;
    int btrow = tid >> 1, bcol = (tid & 1) * 64;

    const char* Ab = (const char*)(A  + (size_t)(bm   + arow)  * K) + acol;
    const char* Bb = (const char*)(Bt + (size_t)(brow + btrow) * K) + bcol;
    uint32_t smbase = smem_u32(sm);
    uint32_t sAa = smbase + (uint32_t)(arow * PITCH_B + acol);
    uint32_t sBa = smbase + A_TILE_BYTES + (uint32_t)(btrow * PITCH_B + bcol);

    auto prefetch = [&](int kt) {
        uint32_t off = (uint32_t)((kt & 1) * STAGE_BYTES);
        const char* ag = Ab + (size_t)kt * 128;     // BK halfs = 128 B
        const char* bg = Bb + (size_t)kt * 128;
        CP_ASYNC16(sAa + off,      ag);
        CP_ASYNC16(sAa + off + 64, ag + 64);
#pragma unroll
        for (int s = 0; s < 4; s++)
            CP_ASYNC16(sBa + off + s * 16, bg + s * 16);
    };

    // ldmatrix per-lane addresses
    int r   = lane & 7;
    int sel = lane >> 3;
    uint32_t aAddr[2], bAddr[2];
#pragma unroll
    for (int mi = 0; mi < 2; mi++)
        aAddr[mi] = smbase +
            (uint32_t)(wm * 32 + mi * 16 + r + (sel & 1) * 8) * PITCH_B + (sel >> 1) * 16;
#pragma unroll
    for (int ni2 = 0; ni2 < 2; ni2++)
        bAddr[ni2] = smbase + A_TILE_BYTES +
            (uint32_t)(wn * 32 + ni2 * 16 + r + (sel >> 1) * 8) * PITCH_B + (sel & 1) * 16;

    float acc[2][4][4];
#pragma unroll
    for (int mi = 0; mi < 2; mi++)
#pragma unroll
        for (int ni = 0; ni < 4; ni++)
#pragma unroll
            for (int c = 0; c < 4; c++) acc[mi][ni][c] = 0.f;

    prefetch(0);
    CP_COMMIT();

    for (int kt = 0; kt < KT; kt++) {
        CP_WAIT0();
        __syncthreads();

        if (kt + 1 < KT) {
            prefetch(kt + 1);
            CP_COMMIT();
        }

        uint32_t stoff = (uint32_t)((kt & 1) * STAGE_BYTES);

#pragma unroll
        for (int ka = 0; ka < 4; ka++) {
            uint32_t koff = stoff + ka * 32;       // one k16 step = 32 bytes
            uint32_t bf[4][2];
            LDSM_X4(bf[0][0], bf[0][1], bf[1][0], bf[1][1], bAddr[0] + koff);
            LDSM_X4(bf[2][0], bf[2][1], bf[3][0], bf[3][1], bAddr[1] + koff);
#pragma unroll
            for (int mi = 0; mi < 2; mi++) {
                uint32_t a0, a1, a2, a3;
                LDSM_X4(a0, a1, a2, a3, aAddr[mi] + koff);
#pragma unroll
                for (int ni = 0; ni < 4; ni++)
                    mma_f16(acc[mi][ni][0], acc[mi][ni][1], acc[mi][ni][2], acc[mi][ni][3],
                            a0, a1, a2, a3, bf[ni][0], bf[ni][1]);
            }
        }
    }

    // ---- epilogue ----
#pragma unroll
    for (int mi = 0; mi < 2; mi++) {
#pragma unroll
        for (int half = 0; half < 2; half++) {
            int row = bm + wm * 32 + mi * 16 + g + half * 8;
#pragma unroll
            for (int ni = 0; ni < 4; ni++) {
                int col = bn + wn * 32 + ni * 8 + tg * 2;
                float v0 = acc[mi][ni][half * 2 + 0];
                float v1 = acc[mi][ni][half * 2 + 1];
                if constexpr (MODE == 0) {
                    const float2 rv = *(const float2*)&res[(size_t)row * 2048 + col];
                    v0 += rv.x; v1 += rv.y;
                    float2 o; o.x = v0; o.y = v1;
                    *(float2*)&((float*)Cout)[(size_t)row * Ncol + col] = o;
                } else if constexpr (MODE == 1) {
                    v0 = fmaxf(v0 + bias[col],     0.f);
                    v1 = fmaxf(v1 + bias[col + 1], 0.f);
                    __half2 h = __floats2half2_rn(v0, v1);
                    *(__half2*)&((__half*)Cout)[(size_t)row * Ncol + col] = h;
                } else {
                    const float2 rv = *(const float2*)&res[(size_t)row * 256 + col];
                    v0 += bias[col]     + rv.x;
                    v1 += bias[col + 1] + rv.y;
                    float2 o; o.x = v0; o.y = v1;
                    *(float2*)&((float*)Cout)[(size_t)row * Ncol + col] = o;
                }
            }
        }
    }
}

// ---------------------------------------------------------------------------
// Host side
// ---------------------------------------------------------------------------
extern "C" void kernel_launch(void* const* d_in, const int* in_sizes, int n_in,
                              void* d_out, int out_size)
{
    const float* ent    = (const float*)d_in[0];
    const float* w_in   = (const float*)d_in[1];
    const float* w_out  = (const float*)d_in[2];
    const float* W1     = (const float*)d_in[3];
    const float* bias1  = (const float*)d_in[4];
    const float* W2     = (const float*)d_in[5];
    const float* bias2  = (const float*)d_in[6];
    const float* gamma1 = (const float*)d_in[7];
    const float* beta1  = (const float*)d_in[8];
    const float* gamma2 = (const float*)d_in[9];
    const float* beta2  = (const float*)d_in[10];
    float* out = (float*)d_out;

    void* p_x;
    void* p_hid;
    cudaGetSymbolAddress(&p_x,   g_x);
    cudaGetSymbolAddress(&p_hid, g_hidden);

    static bool attr_done = false;
    if (!attr_done) {
        cudaFuncSetAttribute(gemm_mma<0>, cudaFuncAttributeMaxDynamicSharedMemorySize, GEMM_SMEM);
        cudaFuncSetAttribute(gemm_mma<1>, cudaFuncAttributeMaxDynamicSharedMemorySize, GEMM_SMEM);
        cudaFuncSetAttribute(gemm_mma<2>, cudaFuncAttributeMaxDynamicSharedMemorySize, GEMM_SMEM);
        attr_done = true;
    }

    // 1. expand circulant weights + round W1/W2 to fp16
    expand_w<<<(NDIM * NDIM + 255) / 256, 256>>>(w_in, w_out);
    round_w<<<(FFD * DD) / 256, 256>>>(W1, W2);

    // 2. LN1: ent -> g_xn (fp16)
    ln_kernel<0><<<ROWS / 8, 256>>>(ent, gamma1, beta1);

    // 3. TT GEMM + residual: g_x = ent + g_xn @ Wbig^T  (4096 x 2048)
    gemm_mma<0><<<dim3(2048 / BN, 4096 / BM), 256, GEMM_SMEM>>>(nullptr, ent, p_x);

    // 4. LN2: g_x -> g_yn (fp16)
    ln_kernel<1><<<ROWS / 8, 256>>>(nullptr, gamma2, beta2);

    // 5. FFN1: g_hidden = fp16(relu(g_yn @ W1^T + b1))  (32768 x 2048)
    gemm_mma<1><<<dim3(2048 / BN, 32768 / BM), 256, GEMM_SMEM>>>(bias1, nullptr, p_hid);

    // 6. FFN2: out = g_x + g_hidden @ W2^T + b2  (32768 x 256)
    gemm_mma<2><<<dim3(256 / BN, 32768 / BM), 256, GEMM_SMEM>>>(bias2, (const float*)p_x, out);
}

// round 16
// speedup vs baseline: 2.0954x; 1.1597x over previous
#include <cuda_runtime.h>
#include <cuda_fp16.h>
#include <cstdint>

// ---------------------------------------------------------------------------
// Problem constants
// ---------------------------------------------------------------------------
#define BB   4096
#define NN   8
#define DD   256
#define FFD  2048
#define NDIM 2048          // N*D
#define ROWS 32768         // B*N

// ---------------------------------------------------------------------------
// Scratch (device globals — no runtime allocation allowed)
// ---------------------------------------------------------------------------
__device__ __half g_wt[2u * NDIM * NDIM];         // expanded circulant weights (fp16, 2 halves stacked)
__device__ __half g_xn[(size_t)BB * NDIM];        // LN1 out (fp16)
__device__ float  g_x [(size_t)BB * NDIM];        // post-TT residual (fp32)
__device__ __half g_yn[(size_t)BB * NDIM];        // LN2 out (fp16)
__device__ __half g_hidden[(size_t)ROWS * FFD];   // FFN hidden (fp16)
__device__ __half g_w1h[FFD * DD];                // W1 fp16
__device__ __half g_w2h[DD * FFD];                // W2 fp16

// ---------------------------------------------------------------------------
// Helpers
// ---------------------------------------------------------------------------
__device__ __forceinline__ uint32_t smem_u32(const void* p) {
    uint32_t a;
    asm("{ .reg .u64 t; cvta.to.shared.u64 t, %1; cvt.u32.u64 %0, t; }"
        : "=r"(a) : "l"(p));
    return a;
}

#define CP_ASYNC16(dst_u32, src_ptr) \
    asm volatile("cp.async.cg.shared.global [%0], [%1], 16;" \
                 :: "r"(dst_u32), "l"(src_ptr) : "memory")
#define CP_COMMIT() asm volatile("cp.async.commit_group;" ::: "memory")
#define CP_WAIT1()  asm volatile("cp.async.wait_group 1;" ::: "memory")
#define CP_WAIT0()  asm volatile("cp.async.wait_group 0;" ::: "memory")

#define LDSM_X4(r0, r1, r2, r3, addr) \
    asm volatile("ldmatrix.sync.aligned.m8n8.x4.shared.b16 {%0,%1,%2,%3}, [%4];" \
                 : "=r"(r0), "=r"(r1), "=r"(r2), "=r"(r3) : "r"(addr))

// fp16 MMA, fp32 accumulate: m16n8k16
__device__ __forceinline__ void mma_f16(float& c0, float& c1, float& c2, float& c3,
                                        uint32_t a0, uint32_t a1, uint32_t a2, uint32_t a3,
                                        uint32_t b0, uint32_t b1) {
    asm volatile(
        "mma.sync.aligned.m16n8k16.row.col.f32.f16.f16.f32 "
        "{%0,%1,%2,%3}, {%4,%5,%6,%7}, {%8,%9}, {%0,%1,%2,%3};"
        : "+f"(c0), "+f"(c1), "+f"(c2), "+f"(c3)
        : "r"(a0), "r"(a1), "r"(a2), "r"(a3), "r"(b0), "r"(b1));
}

// ---------------------------------------------------------------------------
// Weight expansion + rounding (fp16 outputs)
// Wt[jcol = kk*D+o][p = i*D+d] = w[d,o,(kk-i)%8]
// ---------------------------------------------------------------------------
__global__ void expand_w(const float* __restrict__ w_in, const float* __restrict__ w_out)
{
    int idx = blockIdx.x * blockDim.x + threadIdx.x;
    if (idx >= NDIM * NDIM) return;
    int j = idx >> 11;
    int p = idx & 2047;
    int kk = j >> 8, o = j & 255;
    int i  = p >> 8, d = p & 255;
    int s  = (kk - i + 8) & 7;
    int widx = (d * DD + o) * NN + s;
    g_wt[idx]               = __float2half_rn(w_in [widx]);
    g_wt[NDIM * NDIM + idx] = __float2half_rn(w_out[widx]);
}

__global__ void round_w(const float* __restrict__ W1, const float* __restrict__ W2)
{
    int idx = blockIdx.x * blockDim.x + threadIdx.x;
    g_w1h[idx] = __float2half_rn(W1[idx]);
    g_w2h[idx] = __float2half_rn(W2[idx]);
}

// ---------------------------------------------------------------------------
// LayerNorm over D=256, one warp per row; fp16 output
// ---------------------------------------------------------------------------
template<int PH>
__global__ __launch_bounds__(256) void ln_kernel(const float* __restrict__ xin_ext,
                                                 const float* __restrict__ gamma,
                                                 const float* __restrict__ beta)
{
    const float* x    = (PH == 0) ? xin_ext : g_x;
    __half*      out  = (PH == 0) ? g_xn    : g_yn;

    int warp = threadIdx.x >> 5;
    int lane = threadIdx.x & 31;
    int row  = blockIdx.x * 8 + warp;

    const float* xr = x + (size_t)row * DD;
    float v[8];
    float sum = 0.f;
#pragma unroll
    for (int i = 0; i < 8; i++) { v[i] = xr[lane + 32 * i]; sum += v[i]; }
#pragma unroll
    for (int off = 16; off; off >>= 1) sum += __shfl_xor_sync(0xffffffffu, sum, off);
    float mu = sum * (1.f / 256.f);

    float var = 0.f;
#pragma unroll
    for (int i = 0; i < 8; i++) { float t = v[i] - mu; var += t * t; }
#pragma unroll
    for (int off = 16; off; off >>= 1) var += __shfl_xor_sync(0xffffffffu, var, off);
    float rstd = rsqrtf(var * (1.f / 256.f) + 1e-5f);

    __half* orow = out + (size_t)row * DD;
#pragma unroll
    for (int i = 0; i < 8; i++) {
        int c = lane + 32 * i;
        orow[c] = __float2half_rn((v[i] - mu) * rstd * gamma[c] + beta[c]);
    }
}

// ---------------------------------------------------------------------------
// fp16 mma.sync (m16n8k16) GEMM, 3 CTAs/SM (24 warps), XOR-swizzled smem
// (no padding), 3-stage cp.async pipeline (2 tile loads in flight).
// BM=64 BN=128 BK=64 halfs, 256 threads = 2(M) x 4(N) warps, warp tile 32x32.
//
// Swizzle: 128B rows, 16B chunk c of row r stored at chunk c^(r&7).
// For ldmatrix, every lane's row has low-3-bits == lane&7, so the read
// chunk index is (kchunk ^ (lane&7)) — one precomputed XOR operand per lane.
//
// MODE 0: TT (A=g_xn K=2048, Bt=g_wt rows [bn + halfsel*2048], +res(ent) -> g_x fp32)
// MODE 1: FFN1 (A=g_yn K=256, Bt=g_w1h, relu(+bias1) -> g_hidden fp16)
// MODE 2: FFN2 (A=g_hidden K=2048, Bt=g_w2h, +bias2 +g_x -> out fp32)
// ---------------------------------------------------------------------------
#define BM 64
#define BN 128
#define BK 64
#define ROWB 128                           // bytes per smem row (no pad)
#define A_TILE_BYTES (64 * ROWB)           // 8192
#define B_TILE_BYTES (128 * ROWB)          // 16384
#define STAGE_BYTES (A_TILE_BYTES + B_TILE_BYTES)  // 24576
#define NSTAGE 3
#define GEMM_SMEM (NSTAGE * STAGE_BYTES)   // 73728

template<int MODE>
__global__ __launch_bounds__(256, 3) void gemm_mma(
    const float* __restrict__ bias,
    const float* __restrict__ res,
    void* __restrict__ Cout)
{
    constexpr int K    = (MODE == 1) ? 256 : 2048;
    constexpr int Ncol = (MODE == 2) ? 256 : 2048;
    constexpr int KT   = K / BK;          // 32 / 4 / 32

    const __half* A;
    const __half* Bt;
    if constexpr (MODE == 0)      { A = g_xn;     Bt = g_wt;  }
    else if constexpr (MODE == 1) { A = g_yn;     Bt = g_w1h; }
    else                          { A = g_hidden; Bt = g_w2h; }

    extern __shared__ char sm[];

    int tid  = threadIdx.x;
    int wid  = tid >> 5;
    int lane = tid & 31;
    int g    = lane >> 2;
    int tg   = lane & 3;
    int wm   = wid & 1;       // M warp (0..1), 32 rows each
    int wn   = wid >> 1;      // N warp (0..3), 32 cols each

    int bm = blockIdx.y * BM;
    int bn = blockIdx.x * BN;
    int brow = bn;
    if (MODE == 0 && bm >= 2048) brow += 2048;   // second-half weight block

    uint32_t smbase = smem_u32(sm);

    // ---- cp.async mapping (swizzled stores) ----
    // A: 64 rows x 8 chunks; thread t: row = t>>2, chunks c0 = t&3 and c0+4.
    //    swizzled offsets: (c0^(r&7))*16 and ((c0+4)^(r&7))*16 = prev ^ 64.
    // B: 128 rows x 8 chunks; thread t: row = t>>1, chunks (t&1)*4 + s, s=0..3.
    int arow = tid >> 2;
    int ac0  = tid & 3;
    uint32_t aswz0 = (uint32_t)((ac0 ^ (arow & 7)) * 16);
    int btrow = tid >> 1;
    int bc0   = (tid & 1) * 4;

    const char* Ab = (const char*)(A  + (size_t)(bm   + arow)  * K) + ac0 * 16;
    const char* Bb = (const char*)(Bt + (size_t)(brow + btrow) * K) + bc0 * 16;
    uint32_t sArow = smbase + (uint32_t)(arow * ROWB);
    uint32_t sBrow = smbase + A_TILE_BYTES + (uint32_t)(btrow * ROWB);

    auto prefetch = [&](int kt) {
        uint32_t off = (uint32_t)((kt % NSTAGE) * STAGE_BYTES);
        const char* ag = Ab + (size_t)kt * 128;     // BK halfs = 128 B
        const char* bg = Bb + (size_t)kt * 128;
        CP_ASYNC16(sArow + off + aswz0,        ag);
        CP_ASYNC16(sArow + off + (aswz0 ^ 64), ag + 64);
#pragma unroll
        for (int s = 0; s < 4; s++) {
            uint32_t bs = (uint32_t)(((bc0 + s) ^ (btrow & 7)) * 16);
            CP_ASYNC16(sBrow + off + bs, bg + s * 16);
        }
    };

    // ---- ldmatrix per-lane bases (stage offset + swizzled chunk added at use)
    int r   = lane & 7;
    int sel = lane >> 3;
    int aq  = sel >> 1;       // A: kchunk lsb
    int bq  = sel & 1;        // B: kchunk lsb
    uint32_t aRowBase[2], bRowBase[2];
#pragma unroll
    for (int mi = 0; mi < 2; mi++)
        aRowBase[mi] = smbase +
            (uint32_t)(wm * 32 + mi * 16 + r + (sel & 1) * 8) * ROWB;
#pragma unroll
    for (int ni2 = 0; ni2 < 2; ni2++)
        bRowBase[ni2] = smbase + A_TILE_BYTES +
            (uint32_t)(wn * 32 + ni2 * 16 + r + (sel >> 1) * 8) * ROWB;

    float acc[2][4][4];
#pragma unroll
    for (int mi = 0; mi < 2; mi++)
#pragma unroll
        for (int ni = 0; ni < 4; ni++)
#pragma unroll
            for (int c = 0; c < 4; c++) acc[mi][ni][c] = 0.f;

    // ---- prologue: two tile loads in flight ----
    prefetch(0); CP_COMMIT();
    if (KT > 1) { prefetch(1); CP_COMMIT(); }

    for (int kt = 0; kt < KT; kt++) {
        if (kt + 1 < KT) CP_WAIT1(); else CP_WAIT0();
        __syncthreads();   // tile kt visible to all; stage (kt+2)%3 reusable

        if (kt + 2 < KT) {
            prefetch(kt + 2);
            CP_COMMIT();
        }

        uint32_t stoff = (uint32_t)((kt % NSTAGE) * STAGE_BYTES);

#pragma unroll
        for (int ka = 0; ka < 4; ka++) {
            uint32_t offA = (uint32_t)((((ka * 2) | aq) ^ r) * 16) + stoff;
            uint32_t offB = (uint32_t)((((ka * 2) | bq) ^ r) * 16) + stoff;
            uint32_t bf[4][2];
            LDSM_X4(bf[0][0], bf[0][1], bf[1][0], bf[1][1], bRowBase[0] + offB);
            LDSM_X4(bf[2][0], bf[2][1], bf[3][0], bf[3][1], bRowBase[1] + offB);
#pragma unroll
            for (int mi = 0; mi < 2; mi++) {
                uint32_t a0, a1, a2, a3;
                LDSM_X4(a0, a1, a2, a3, aRowBase[mi] + offA);
#pragma unroll
                for (int ni = 0; ni < 4; ni++)
                    mma_f16(acc[mi][ni][0], acc[mi][ni][1], acc[mi][ni][2], acc[mi][ni][3],
                            a0, a1, a2, a3, bf[ni][0], bf[ni][1]);
            }
        }
    }

    // ---- epilogue ----
#pragma unroll
    for (int mi = 0; mi < 2; mi++) {
#pragma unroll
        for (int half = 0; half < 2; half++) {
            int row = bm + wm * 32 + mi * 16 + g + half * 8;
#pragma unroll
            for (int ni = 0; ni < 4; ni++) {
                int col = bn + wn * 32 + ni * 8 + tg * 2;
                float v0 = acc[mi][ni][half * 2 + 0];
                float v1 = acc[mi][ni][half * 2 + 1];
                if constexpr (MODE == 0) {
                    const float2 rv = *(const float2*)&res[(size_t)row * 2048 + col];
                    v0 += rv.x; v1 += rv.y;
                    float2 o; o.x = v0; o.y = v1;
                    *(float2*)&((float*)Cout)[(size_t)row * Ncol + col] = o;
                } else if constexpr (MODE == 1) {
                    v0 = fmaxf(v0 + bias[col],     0.f);
                    v1 = fmaxf(v1 + bias[col + 1], 0.f);
                    __half2 h = __floats2half2_rn(v0, v1);
                    *(__half2*)&((__half*)Cout)[(size_t)row * Ncol + col] = h;
                } else {
                    const float2 rv = *(const float2*)&res[(size_t)row * 256 + col];
                    v0 += bias[col]     + rv.x;
                    v1 += bias[col + 1] + rv.y;
                    float2 o; o.x = v0; o.y = v1;
                    *(float2*)&((float*)Cout)[(size_t)row * Ncol + col] = o;
                }
            }
        }
    }
}

// ---------------------------------------------------------------------------
// Host side
// ---------------------------------------------------------------------------
extern "C" void kernel_launch(void* const* d_in, const int* in_sizes, int n_in,
                              void* d_out, int out_size)
{
    const float* ent    = (const float*)d_in[0];
    const float* w_in   = (const float*)d_in[1];
    const float* w_out  = (const float*)d_in[2];
    const float* W1     = (const float*)d_in[3];
    const float* bias1  = (const float*)d_in[4];
    const float* W2     = (const float*)d_in[5];
    const float* bias2  = (const float*)d_in[6];
    const float* gamma1 = (const float*)d_in[7];
    const float* beta1  = (const float*)d_in[8];
    const float* gamma2 = (const float*)d_in[9];
    const float* beta2  = (const float*)d_in[10];
    float* out = (float*)d_out;

    void* p_x;
    void* p_hid;
    cudaGetSymbolAddress(&p_x,   g_x);
    cudaGetSymbolAddress(&p_hid, g_hidden);

    static bool attr_done = false;
    if (!attr_done) {
        cudaFuncSetAttribute(gemm_mma<0>, cudaFuncAttributeMaxDynamicSharedMemorySize, GEMM_SMEM);
        cudaFuncSetAttribute(gemm_mma<1>, cudaFuncAttributeMaxDynamicSharedMemorySize, GEMM_SMEM);
        cudaFuncSetAttribute(gemm_mma<2>, cudaFuncAttributeMaxDynamicSharedMemorySize, GEMM_SMEM);
        attr_done = true;
    }

    // 1. expand circulant weights + round W1/W2 to fp16
    expand_w<<<(NDIM * NDIM + 255) / 256, 256>>>(w_in, w_out);
    round_w<<<(FFD * DD) / 256, 256>>>(W1, W2);

    // 2. LN1: ent -> g_xn (fp16)
    ln_kernel<0><<<ROWS / 8, 256>>>(ent, gamma1, beta1);

    // 3. TT GEMM + residual: g_x = ent + g_xn @ Wbig^T  (4096 x 2048)
    gemm_mma<0><<<dim3(2048 / BN, 4096 / BM), 256, GEMM_SMEM>>>(nullptr, ent, p_x);

    // 4. LN2: g_x -> g_yn (fp16)
    ln_kernel<1><<<ROWS / 8, 256>>>(nullptr, gamma2, beta2);

    // 5. FFN1: g_hidden = fp16(relu(g_yn @ W1^T + b1))  (32768 x 2048)
    gemm_mma<1><<<dim3(2048 / BN, 32768 / BM), 256, GEMM_SMEM>>>(bias1, nullptr, p_hid);

    // 6. FFN2: out = g_x + g_hidden @ W2^T + b2  (32768 x 256)
    gemm_mma<2><<<dim3(256 / BN, 32768 / BM), 256, GEMM_SMEM>>>(bias2, (const float*)p_x, out);
}